// round 12
// baseline (speedup 1.0000x reference)
#include <cuda_runtime.h>
#include <cuda_bf16.h>
#include <cstdint>

// ===========================================================================
// NT-Xent (SimCLR) loss, B=4096, D=256, T=0.5  ->  N=8192 rows, K=256.
//
// R11 = R8 (best: 59.5us) with simexp made PERSISTENT (296 CTAs, dynamic
// tile pop) and the cp.async pipeline running CONTINUOUSLY across tile
// boundaries: 3 stages, prefetch distance 2 chunks, exactly one commit per
// chunk (empty groups at stream end), cp_wait<1> always -- the R5 mistake
// (cp_wait<0> draining the just-issued next-tile prefetch) is avoided.
// Removes the ~6us wave-quantization tail (2080 tiles / 296 slots = 7.03).
//
// Pop protocol: tid0 atomicAdd at chunk 0 into s_next[parity]; all threads
// read it after the chunk-2 barrier (2 chunks of slack hides the latency).
// Deterministic output: each tile writes unique g_rowpart slots.
//
// dtype levers dead (R7 fp8: 64.0, R9 fp16: 64.2); bf16 + f32 accum kept.
// Triangle trick: 2080 upper 128x128 tiles; off-diag tiles emit row+col sums.
// Logit scale folded into inputs (zb = z_hat*sqrt(2*log2 e)); diagonal
// subtracted later with the SAME ex2 formula (cancels to rounding).
// ===========================================================================

#define N_TOTAL 8192
#define DK      256
#define TILE    128
#define NTILES  64
#define NSLOTS  (NTILES * 2)                    // 128 partial slots per row
#define NTRI    (NTILES * (NTILES + 1) / 2)     // 2080 triangle tiles
#define NPCTA   296                             // 2 CTAs x 148 SMs

#define SCALE_S 1.6986435987381852f             // sqrt(2*log2(e))

__device__ __nv_bfloat16 g_zb[(size_t)N_TOTAL * DK];        // 4 MB
__device__ float g_rowpart[(size_t)N_TOTAL * NSLOTS];       // 4 MB
__device__ float g_partial[1024];
__device__ int   g_tilectr;
__device__ int   g_done;

// ---------------------------------------------------------------------------
__device__ __forceinline__ uint32_t smem_u32(const void* p) {
    uint32_t a;
    asm("{ .reg .u64 t; cvta.to.shared.u64 t, %1; cvt.u32.u64 %0, t; }"
        : "=r"(a) : "l"(p));
    return a;
}

__device__ __forceinline__ float fast_exp2(float x) {
    float y;
    asm("ex2.approx.f32 %0, %1;" : "=f"(y) : "f"(x));
    return y;
}

#define LDSM_X4(r, addr) \
    asm volatile("ldmatrix.sync.aligned.m8n8.x4.shared.b16 {%0,%1,%2,%3}, [%4];" \
        : "=r"((r)[0]), "=r"((r)[1]), "=r"((r)[2]), "=r"((r)[3]) : "r"(addr))

#define MMA16816(c, a, b0v, b1v) \
    asm volatile("mma.sync.aligned.m16n8k16.row.col.f32.bf16.bf16.f32 " \
        "{%0,%1,%2,%3}, {%4,%5,%6,%7}, {%8,%9}, {%0,%1,%2,%3};" \
        : "+f"((c)[0]), "+f"((c)[1]), "+f"((c)[2]), "+f"((c)[3]) \
        : "r"((a)[0]), "r"((a)[1]), "r"((a)[2]), "r"((a)[3]), \
          "r"(b0v), "r"(b1v))

__device__ __forceinline__ void cp16(uint32_t saddr, const void* gptr) {
    uint64_t g;
    asm volatile("cvta.to.global.u64 %0, %1;" : "=l"(g) : "l"(gptr));
    asm volatile("cp.async.cg.shared.global [%0], [%1], 16;"
                 :: "r"(saddr), "l"(g) : "memory");
}
template <int N>
__device__ __forceinline__ void cp_wait() {
    asm volatile("cp.async.wait_group %0;" :: "n"(N) : "memory");
}
__device__ __forceinline__ void cp_commit() {
    asm volatile("cp.async.commit_group;" ::: "memory");
}

// ---------------------------------------------------------------------------
// Kernel 1: normalize rows -> bf16 (pre-scaled by SCALE_S), reset counters.
// ---------------------------------------------------------------------------
__global__ __launch_bounds__(256) void normalize_kernel(
    const float* __restrict__ zi, const float* __restrict__ zj)
{
    if (blockIdx.x == 0 && threadIdx.x == 0) { g_done = 0; g_tilectr = NPCTA; }
    int row  = blockIdx.x * 8 + (threadIdx.x >> 5);
    int lane = threadIdx.x & 31;
    const float* src = (row < 4096) ? zi + (size_t)row * DK
                                    : zj + (size_t)(row - 4096) * DK;
    float4 v0 = reinterpret_cast<const float4*>(src)[lane * 2];
    float4 v1 = reinterpret_cast<const float4*>(src)[lane * 2 + 1];
    float ss = v0.x * v0.x + v0.y * v0.y + v0.z * v0.z + v0.w * v0.w
             + v1.x * v1.x + v1.y * v1.y + v1.z * v1.z + v1.w * v1.w;
    #pragma unroll
    for (int o = 16; o; o >>= 1) ss += __shfl_xor_sync(0xffffffffu, ss, o);
    float rn = rsqrtf(ss) * SCALE_S;

    __nv_bfloat162 p0 = __floats2bfloat162_rn(v0.x * rn, v0.y * rn);
    __nv_bfloat162 p1 = __floats2bfloat162_rn(v0.z * rn, v0.w * rn);
    __nv_bfloat162 p2 = __floats2bfloat162_rn(v1.x * rn, v1.y * rn);
    __nv_bfloat162 p3 = __floats2bfloat162_rn(v1.z * rn, v1.w * rn);
    uint4 o4;
    o4.x = *reinterpret_cast<uint32_t*>(&p0);
    o4.y = *reinterpret_cast<uint32_t*>(&p1);
    o4.z = *reinterpret_cast<uint32_t*>(&p2);
    o4.w = *reinterpret_cast<uint32_t*>(&p3);
    reinterpret_cast<uint4*>(g_zb + (size_t)row * DK)[lane] = o4;
}

// ---------------------------------------------------------------------------
// Kernel 2: persistent upper-triangle 128x128 HMMA tiles + exp row/col sums.
// 296 persistent CTAs, 256 threads (8 warps, 4(M) x 2(N), warp tile 32x64).
// Continuous 3-stage cp.async chunk stream across tiles, distance 2,
// one commit + one __syncthreads per chunk.
// ---------------------------------------------------------------------------
#define KCHUNK      64
#define MAT_BYTES   (TILE * KCHUNK * 2)          // 16384
#define STAGE_BYTES (2 * MAT_BYTES)              // 32768
#define NSTAGE      3
#define CW_OFF      (NSTAGE * STAGE_BYTES)       // 98304
#define SMEM_BYTES  (CW_OFF + 2048)              // 100352 (x2 <= 228KB)

__device__ __forceinline__ uint32_t sw_off(int r, int kg) {
    return (uint32_t)(r * 128 + ((kg ^ (r & 7)) << 4));
}

__device__ __forceinline__ void decode_tile(int t, int& x, int& y) {
    int xx = __float2int_rd((129.0f - sqrtf(16641.0f - 8.0f * (float)t)) * 0.5f);
    if (xx > 63) xx = 63;
    if (xx < 0)  xx = 0;
    while (xx > 0 && xx * (129 - xx) / 2 > t) --xx;
    while ((xx + 1) * (129 - (xx + 1)) / 2 <= t) ++xx;
    x = xx;
    y = xx + (t - xx * (129 - xx) / 2);
}

__device__ __forceinline__ void prefetch_chunk(
    uint32_t sbase, int stage, int row0, int col0, int chunk, int tid)
{
    #pragma unroll
    for (int i = 0; i < 8; ++i) {
        int v   = tid + i * 256;         // 0..2047
        int mat = v >> 10;               // 0 = A, 1 = B
        int r   = (v >> 3) & 127;
        int kg  = v & 7;
        int grow = (mat ? col0 : row0) + r;
        const __nv_bfloat16* g = g_zb + (size_t)grow * DK + chunk * KCHUNK + kg * 8;
        uint32_t s = sbase + stage * STAGE_BYTES + mat * MAT_BYTES + sw_off(r, kg);
        cp16(s, g);
    }
    cp_commit();
}

__global__ __launch_bounds__(256, 2) void simexp_kernel() {
    extern __shared__ char smem[];
    __shared__ int s_next[2];
    const uint32_t sbase = smem_u32(smem);
    const int tid  = threadIdx.x;
    const int warp = tid >> 5;
    const int lane = tid & 31;
    const int warp_m = (warp >> 1) * 32;
    const int warp_n = (warp & 1) * 64;

    int t = blockIdx.x;                 // first tile is static
    int x, y;
    decode_tile(t, x, y);
    int row0 = x * TILE, col0 = y * TILE;

    // prologue: chunks 0,1 of first tile -> stages 0,1 (2 groups in flight)
    prefetch_chunk(sbase, 0, row0, col0, 0, tid);
    prefetch_chunk(sbase, 1, row0, col0, 1, tid);

    int sidx   = 0;                     // stage of next chunk to consume
    int parity = 0;

    while (t < NTRI) {
        float acc[2][8][4];
        #pragma unroll
        for (int mf = 0; mf < 2; ++mf)
            #pragma unroll
            for (int nf = 0; nf < 8; ++nf)
                #pragma unroll
                for (int q = 0; q < 4; ++q) acc[mf][nf][q] = 0.f;

        int t2 = NTRI, nrow0 = 0, ncol0 = 0, nx = 0, ny = 0;

        #pragma unroll
        for (int c = 0; c < 4; ++c) {
            cp_wait<1>();               // chunk at stage sidx resident;
            __syncthreads();            // all warps done with stage sidx-1

            if (c == 0 && tid == 0)     // pop next tile; 2 chunks of slack
                s_next[parity] = atomicAdd(&g_tilectr, 1);

            const int pstage = (sidx + 2) % NSTAGE;
            if (c < 2) {
                prefetch_chunk(sbase, pstage, row0, col0, c + 2, tid);
            } else if (c == 2) {
                t2 = s_next[parity];    // visible: written before c==1 barrier
                if (t2 < NTRI) {
                    decode_tile(t2, nx, ny);
                    nrow0 = nx * TILE; ncol0 = ny * TILE;
                    prefetch_chunk(sbase, pstage, nrow0, ncol0, 0, tid);
                } else cp_commit();     // keep group counting consistent
            } else {                    // c == 3
                if (t2 < NTRI) prefetch_chunk(sbase, pstage, nrow0, ncol0, 1, tid);
                else cp_commit();
            }

            const uint32_t abase = sbase + sidx * STAGE_BYTES;
            const uint32_t bbase = abase + MAT_BYTES;

            #pragma unroll
            for (int ks = 0; ks < 4; ++ks) {
                uint32_t afr[2][4];
                #pragma unroll
                for (int mf = 0; mf < 2; ++mf) {
                    int r  = warp_m + mf * 16 + (lane & 15);
                    int kg = 2 * ks + (lane >> 4);
                    LDSM_X4(afr[mf], abase + sw_off(r, kg));
                }
                uint32_t bfr[4][4];
                #pragma unroll
                for (int nb = 0; nb < 4; ++nb) {
                    int n  = warp_n + nb * 16 + ((lane >> 4) << 3) + (lane & 7);
                    int kg = 2 * ks + ((lane >> 3) & 1);
                    LDSM_X4(bfr[nb], bbase + sw_off(n, kg));
                }
                #pragma unroll
                for (int mf = 0; mf < 2; ++mf)
                    #pragma unroll
                    for (int nb = 0; nb < 4; ++nb) {
                        MMA16816(acc[mf][2 * nb    ], afr[mf], bfr[nb][0], bfr[nb][1]);
                        MMA16816(acc[mf][2 * nb + 1], afr[mf], bfr[nb][2], bfr[nb][3]);
                    }
            }
            sidx = (sidx + 1) % NSTAGE;
        }

        // --- Epilogue (next tile's chunks 0,1 already in flight) ---
        float rs[4] = {0.f, 0.f, 0.f, 0.f};
        float cs[8][2];
        #pragma unroll
        for (int nf = 0; nf < 8; ++nf) { cs[nf][0] = 0.f; cs[nf][1] = 0.f; }

        #pragma unroll
        for (int mf = 0; mf < 2; ++mf)
            #pragma unroll
            for (int nf = 0; nf < 8; ++nf) {
                float e0 = fast_exp2(acc[mf][nf][0]);
                float e1 = fast_exp2(acc[mf][nf][1]);
                float e2 = fast_exp2(acc[mf][nf][2]);
                float e3 = fast_exp2(acc[mf][nf][3]);
                rs[mf * 2 + 0] += e0 + e1;
                rs[mf * 2 + 1] += e2 + e3;
                cs[nf][0] += e0 + e2;
                cs[nf][1] += e1 + e3;
            }

        #pragma unroll
        for (int o = 1; o < 4; o <<= 1)
            #pragma unroll
            for (int q = 0; q < 4; ++q)
                rs[q] += __shfl_xor_sync(0xffffffffu, rs[q], o);
        if ((lane & 3) == 0) {
            int g    = lane >> 2;
            int slot = 2 * y + (warp & 1);
            g_rowpart[(size_t)(row0 + warp_m +  0 + g) * NSLOTS + slot] = rs[0];
            g_rowpart[(size_t)(row0 + warp_m +  8 + g) * NSLOTS + slot] = rs[1];
            g_rowpart[(size_t)(row0 + warp_m + 16 + g) * NSLOTS + slot] = rs[2];
            g_rowpart[(size_t)(row0 + warp_m + 24 + g) * NSLOTS + slot] = rs[3];
        }

        if (x != y) {
            #pragma unroll
            for (int o = 4; o < 32; o <<= 1)
                #pragma unroll
                for (int nf = 0; nf < 8; ++nf) {
                    cs[nf][0] += __shfl_xor_sync(0xffffffffu, cs[nf][0], o);
                    cs[nf][1] += __shfl_xor_sync(0xffffffffu, cs[nf][1], o);
                }
            float* cw = reinterpret_cast<float*>(smem + CW_OFF);
            if (lane < 4) {
                #pragma unroll
                for (int nf = 0; nf < 8; ++nf) {
                    cw[warp * 64 + nf * 8 + 2 * lane    ] = cs[nf][0];
                    cw[warp * 64 + nf * 8 + 2 * lane + 1] = cs[nf][1];
                }
            }
            __syncthreads();
            int j  = tid & 63;
            int h  = (tid >> 6) & 1;
            int mp = tid >> 7;
            float v = cw[(h + 4 * mp) * 64 + j] + cw[(h + 4 * mp + 2) * 64 + j];
            g_rowpart[(size_t)(col0 + h * 64 + j) * NSLOTS + (2 * x + mp)] = v;
        }

        t = t2; x = nx; y = ny; row0 = nrow0; col0 = ncol0; parity ^= 1;
    }
}

// ---------------------------------------------------------------------------
// Kernel 3: per-row loss term + fused deterministic final reduction
// ---------------------------------------------------------------------------
__global__ __launch_bounds__(256) void rowloss_kernel(float* __restrict__ out) {
    __shared__ float wsum[8];
    __shared__ int s_last;
    int w    = threadIdx.x >> 5;
    int lane = threadIdx.x & 31;
    int row  = blockIdx.x * 8 + w;
    int prow = (row < 4096) ? row + 4096 : row - 4096;

    const float* pp = g_rowpart + (size_t)row * NSLOTS;
    float se = pp[lane] + pp[lane + 32] + pp[lane + 64] + pp[lane + 96];

    uint4 av4 = reinterpret_cast<const uint4*>(g_zb + (size_t)row  * DK)[lane];
    uint4 bv4 = reinterpret_cast<const uint4*>(g_zb + (size_t)prow * DK)[lane];
    float diag = 0.f, pos = 0.f;                 // scaled units
    const uint32_t* au = &av4.x;
    const uint32_t* bu = &bv4.x;
    #pragma unroll
    for (int k = 0; k < 4; ++k) {
        __nv_bfloat162 a2 = *reinterpret_cast<const __nv_bfloat162*>(&au[k]);
        __nv_bfloat162 b2 = *reinterpret_cast<const __nv_bfloat162*>(&bu[k]);
        float ax = __bfloat162float(a2.x), ay = __bfloat162float(a2.y);
        float bx = __bfloat162float(b2.x), by = __bfloat162float(b2.y);
        diag += ax * ax + ay * ay;
        pos  += ax * bx + ay * by;
    }
    #pragma unroll
    for (int o = 16; o; o >>= 1) {
        se   += __shfl_xor_sync(0xffffffffu, se,   o);
        diag += __shfl_xor_sync(0xffffffffu, diag, o);
        pos  += __shfl_xor_sync(0xffffffffu, pos,  o);
    }
    if (lane == 0) {
        float sv = se - fast_exp2(diag);        // same exp formula -> cancels
        wsum[w] = __logf(sv) - pos * 0.6931471805599453f;
    }
    __syncthreads();
    if (threadIdx.x == 0) {
        float s = 0.f;
        #pragma unroll
        for (int i = 0; i < 8; ++i) s += wsum[i];
        g_partial[blockIdx.x] = s;
        __threadfence();
        s_last = (atomicAdd(&g_done, 1) == (int)gridDim.x - 1);
    }
    __syncthreads();

    if (s_last) {
        float s = g_partial[threadIdx.x]
                + g_partial[threadIdx.x + 256]
                + g_partial[threadIdx.x + 512]
                + g_partial[threadIdx.x + 768];
        __shared__ float red[256];
        red[threadIdx.x] = s;
        __syncthreads();
        #pragma unroll
        for (int o = 128; o; o >>= 1) {
            if (threadIdx.x < o) red[threadIdx.x] += red[threadIdx.x + o];
            __syncthreads();
        }
        if (threadIdx.x == 0) out[0] = red[0] * (1.0f / (float)N_TOTAL);
    }
}

// ---------------------------------------------------------------------------
extern "C" void kernel_launch(void* const* d_in, const int* in_sizes, int n_in,
                              void* d_out, int out_size)
{
    const float* zi = (const float*)d_in[0];
    const float* zj = (const float*)d_in[1];
    float* out = (float*)d_out;

    cudaFuncSetAttribute(simexp_kernel,
                         cudaFuncAttributeMaxDynamicSharedMemorySize, SMEM_BYTES);

    normalize_kernel<<<1024, 256>>>(zi, zj);
    simexp_kernel<<<NPCTA, 256, SMEM_BYTES>>>();
    rowloss_kernel<<<1024, 256>>>(out);
}

// round 13
// speedup vs baseline: 1.2563x; 1.2563x over previous
#include <cuda_runtime.h>
#include <cuda_bf16.h>
#include <cstdint>

// ===========================================================================
// NT-Xent (SimCLR) loss, B=4096, D=256, T=0.5  ->  N=8192 rows, K=256.
//
// R12 = R8 simexp mainloop VERBATIM (best: 59.5us; persistence dead per
// R5/R11, dtype levers dead per R7/R9, interleave neutral per R10) with:
//   * g_rowpart transposed to [slot][row]: rs stores were 8x sector-amplified
//     (rows 512B apart); now 1-sector coalesced. Col-sum stores coalesced.
//   * rowloss reworked for the transposed layout (warp sums 16 slots over
//     32 consecutive rows, coalesced; 8 threads/row for diag/pos).
//   * normalize: best-measured shape (grid 1024, one row/warp, 5.57us).
//
// Triangle trick: 2080 upper 128x128 tiles; off-diag tiles emit row+col sums.
// Logit scale folded into inputs (zb = z_hat*sqrt(2*log2 e)); diagonal
// subtracted later with the SAME ex2 formula (cancels to rounding).
// ===========================================================================

#define N_TOTAL 8192
#define DK      256
#define TILE    128
#define NTILES  64
#define NSLOTS  (NTILES * 2)                    // 128 partial slots per row
#define NTRI    (NTILES * (NTILES + 1) / 2)     // 2080 triangle tiles

#define SCALE_S 1.6986435987381852f             // sqrt(2*log2(e))

__device__ __nv_bfloat16 g_zb[(size_t)N_TOTAL * DK];        // 4 MB
__device__ float g_rowpart[(size_t)NSLOTS * N_TOTAL];       // 4 MB, [slot][row]
__device__ float g_partial[256];
__device__ int   g_done;

// ---------------------------------------------------------------------------
__device__ __forceinline__ uint32_t smem_u32(const void* p) {
    uint32_t a;
    asm("{ .reg .u64 t; cvta.to.shared.u64 t, %1; cvt.u32.u64 %0, t; }"
        : "=r"(a) : "l"(p));
    return a;
}

__device__ __forceinline__ float fast_exp2(float x) {
    float y;
    asm("ex2.approx.f32 %0, %1;" : "=f"(y) : "f"(x));
    return y;
}

#define LDSM_X4(r, addr) \
    asm volatile("ldmatrix.sync.aligned.m8n8.x4.shared.b16 {%0,%1,%2,%3}, [%4];" \
        : "=r"((r)[0]), "=r"((r)[1]), "=r"((r)[2]), "=r"((r)[3]) : "r"(addr))

#define MMA16816(c, a, b0v, b1v) \
    asm volatile("mma.sync.aligned.m16n8k16.row.col.f32.bf16.bf16.f32 " \
        "{%0,%1,%2,%3}, {%4,%5,%6,%7}, {%8,%9}, {%0,%1,%2,%3};" \
        : "+f"((c)[0]), "+f"((c)[1]), "+f"((c)[2]), "+f"((c)[3]) \
        : "r"((a)[0]), "r"((a)[1]), "r"((a)[2]), "r"((a)[3]), \
          "r"(b0v), "r"(b1v))

__device__ __forceinline__ void cp16(uint32_t saddr, const void* gptr) {
    uint64_t g;
    asm volatile("cvta.to.global.u64 %0, %1;" : "=l"(g) : "l"(gptr));
    asm volatile("cp.async.cg.shared.global [%0], [%1], 16;"
                 :: "r"(saddr), "l"(g) : "memory");
}
template <int N>
__device__ __forceinline__ void cp_wait() {
    asm volatile("cp.async.wait_group %0;" :: "n"(N) : "memory");
}
__device__ __forceinline__ void cp_commit() {
    asm volatile("cp.async.commit_group;" ::: "memory");
}

// ---------------------------------------------------------------------------
// Kernel 1: normalize rows -> bf16 (pre-scaled by SCALE_S), reset done ctr.
// ---------------------------------------------------------------------------
__global__ __launch_bounds__(256) void normalize_kernel(
    const float* __restrict__ zi, const float* __restrict__ zj)
{
    if (blockIdx.x == 0 && threadIdx.x == 0) g_done = 0;
    int row  = blockIdx.x * 8 + (threadIdx.x >> 5);
    int lane = threadIdx.x & 31;
    const float* src = (row < 4096) ? zi + (size_t)row * DK
                                    : zj + (size_t)(row - 4096) * DK;
    float4 v0 = reinterpret_cast<const float4*>(src)[lane * 2];
    float4 v1 = reinterpret_cast<const float4*>(src)[lane * 2 + 1];
    float ss = v0.x * v0.x + v0.y * v0.y + v0.z * v0.z + v0.w * v0.w
             + v1.x * v1.x + v1.y * v1.y + v1.z * v1.z + v1.w * v1.w;
    #pragma unroll
    for (int o = 16; o; o >>= 1) ss += __shfl_xor_sync(0xffffffffu, ss, o);
    float rn = rsqrtf(ss) * SCALE_S;

    __nv_bfloat162 p0 = __floats2bfloat162_rn(v0.x * rn, v0.y * rn);
    __nv_bfloat162 p1 = __floats2bfloat162_rn(v0.z * rn, v0.w * rn);
    __nv_bfloat162 p2 = __floats2bfloat162_rn(v1.x * rn, v1.y * rn);
    __nv_bfloat162 p3 = __floats2bfloat162_rn(v1.z * rn, v1.w * rn);
    uint4 o4;
    o4.x = *reinterpret_cast<uint32_t*>(&p0);
    o4.y = *reinterpret_cast<uint32_t*>(&p1);
    o4.z = *reinterpret_cast<uint32_t*>(&p2);
    o4.w = *reinterpret_cast<uint32_t*>(&p3);
    reinterpret_cast<uint4*>(g_zb + (size_t)row * DK)[lane] = o4;
}

// ---------------------------------------------------------------------------
// Kernel 2 (R8 mainloop verbatim): upper-triangle 128x128 HMMA tiles +
// exp row/col sums. 2080 CTAs, 256 threads (8 warps, 4(M) x 2(N)).
// K=256 in 4 chunks of 64 via 3-stage cp.async (96 KB smem, 2 CTAs/SM),
// ONE __syncthreads per chunk. Epilogue stores to [slot][row] (coalesced).
// ---------------------------------------------------------------------------
#define KCHUNK      64
#define MAT_BYTES   (TILE * KCHUNK * 2)          // 16384
#define STAGE_BYTES (2 * MAT_BYTES)              // 32768
#define NSTAGE      3
#define CW_OFF      (NSTAGE * STAGE_BYTES)       // 98304
#define SMEM_BYTES  (CW_OFF + 2048)              // 100352

__device__ __forceinline__ uint32_t sw_off(int r, int kg) {
    return (uint32_t)(r * 128 + ((kg ^ (r & 7)) << 4));
}

__device__ __forceinline__ void prefetch_chunk(
    uint32_t sbase, int stage, int row0, int col0, int chunk, int tid)
{
    #pragma unroll
    for (int i = 0; i < 8; ++i) {
        int v   = tid + i * 256;         // 0..2047
        int mat = v >> 10;               // 0 = A, 1 = B
        int r   = (v >> 3) & 127;
        int kg  = v & 7;
        int grow = (mat ? col0 : row0) + r;
        const __nv_bfloat16* g = g_zb + (size_t)grow * DK + chunk * KCHUNK + kg * 8;
        uint32_t s = sbase + stage * STAGE_BYTES + mat * MAT_BYTES + sw_off(r, kg);
        cp16(s, g);
    }
    cp_commit();
}

__global__ __launch_bounds__(256, 2) void simexp_kernel() {
    extern __shared__ char smem[];
    const uint32_t sbase = smem_u32(smem);
    const int tid  = threadIdx.x;
    const int warp = tid >> 5;
    const int lane = tid & 31;

    // --- decode linear tile id -> (x, y) with y >= x; start(x)=x*(129-x)/2 ---
    const int t = blockIdx.x;
    int x = __float2int_rd((129.0f - sqrtf(16641.0f - 8.0f * (float)t)) * 0.5f);
    if (x > 63) x = 63;
    while (x > 0 && x * (129 - x) / 2 > t) --x;
    while ((x + 1) * (129 - (x + 1)) / 2 <= t) ++x;
    const int y = x + (t - x * (129 - x) / 2);

    const int row0 = x * TILE;
    const int col0 = y * TILE;
    const int warp_m = (warp >> 1) * 32;
    const int warp_n = (warp & 1) * 64;

    float acc[2][8][4];
    #pragma unroll
    for (int mf = 0; mf < 2; ++mf)
        #pragma unroll
        for (int nf = 0; nf < 8; ++nf)
            #pragma unroll
            for (int q = 0; q < 4; ++q) acc[mf][nf][q] = 0.f;

    prefetch_chunk(sbase, 0, row0, col0, 0, tid);
    prefetch_chunk(sbase, 1, row0, col0, 1, tid);

    #pragma unroll
    for (int c = 0; c < 4; ++c) {
        if (c < 3) { cp_wait<1>(); } else { cp_wait<0>(); }
        __syncthreads();                 // chunk c resident; chunk c-1 done by
                                         // all warps -> c+2 prefetch is safe
        if (c + 2 < 4)
            prefetch_chunk(sbase, (c + 2) % NSTAGE, row0, col0, c + 2, tid);

        const uint32_t abase = sbase + (c % NSTAGE) * STAGE_BYTES;
        const uint32_t bbase = abase + MAT_BYTES;

        #pragma unroll
        for (int ks = 0; ks < 4; ++ks) {
            uint32_t afr[2][4];
            #pragma unroll
            for (int mf = 0; mf < 2; ++mf) {
                int r  = warp_m + mf * 16 + (lane & 15);
                int kg = 2 * ks + (lane >> 4);
                LDSM_X4(afr[mf], abase + sw_off(r, kg));
            }
            uint32_t bfr[4][4];
            #pragma unroll
            for (int nb = 0; nb < 4; ++nb) {
                int n  = warp_n + nb * 16 + ((lane >> 4) << 3) + (lane & 7);
                int kg = 2 * ks + ((lane >> 3) & 1);
                LDSM_X4(bfr[nb], bbase + sw_off(n, kg));
            }
            #pragma unroll
            for (int mf = 0; mf < 2; ++mf)
                #pragma unroll
                for (int nb = 0; nb < 4; ++nb) {
                    MMA16816(acc[mf][2 * nb    ], afr[mf], bfr[nb][0], bfr[nb][1]);
                    MMA16816(acc[mf][2 * nb + 1], afr[mf], bfr[nb][2], bfr[nb][3]);
                }
        }
    }

    // --- Epilogue ---
    float rs[4] = {0.f, 0.f, 0.f, 0.f};
    float cs[8][2];
    #pragma unroll
    for (int nf = 0; nf < 8; ++nf) { cs[nf][0] = 0.f; cs[nf][1] = 0.f; }

    #pragma unroll
    for (int mf = 0; mf < 2; ++mf)
        #pragma unroll
        for (int nf = 0; nf < 8; ++nf) {
            float e0 = fast_exp2(acc[mf][nf][0]);
            float e1 = fast_exp2(acc[mf][nf][1]);
            float e2 = fast_exp2(acc[mf][nf][2]);
            float e3 = fast_exp2(acc[mf][nf][3]);
            rs[mf * 2 + 0] += e0 + e1;
            rs[mf * 2 + 1] += e2 + e3;
            cs[nf][0] += e0 + e2;
            cs[nf][1] += e1 + e3;
        }

    #pragma unroll
    for (int o = 1; o < 4; o <<= 1)
        #pragma unroll
        for (int q = 0; q < 4; ++q)
            rs[q] += __shfl_xor_sync(0xffffffffu, rs[q], o);
    if ((lane & 3) == 0) {
        int g    = lane >> 2;
        int slot = 2 * y + (warp & 1);
        // [slot][row] layout: 8 lanes write 8 consecutive floats -> 1 sector
        g_rowpart[(size_t)slot * N_TOTAL + (row0 + warp_m +  0 + g)] = rs[0];
        g_rowpart[(size_t)slot * N_TOTAL + (row0 + warp_m +  8 + g)] = rs[1];
        g_rowpart[(size_t)slot * N_TOTAL + (row0 + warp_m + 16 + g)] = rs[2];
        g_rowpart[(size_t)slot * N_TOTAL + (row0 + warp_m + 24 + g)] = rs[3];
    }

    if (x != y) {
        #pragma unroll
        for (int o = 4; o < 32; o <<= 1)
            #pragma unroll
            for (int nf = 0; nf < 8; ++nf) {
                cs[nf][0] += __shfl_xor_sync(0xffffffffu, cs[nf][0], o);
                cs[nf][1] += __shfl_xor_sync(0xffffffffu, cs[nf][1], o);
            }
        float* cw = reinterpret_cast<float*>(smem + CW_OFF);
        if (lane < 4) {
            #pragma unroll
            for (int nf = 0; nf < 8; ++nf) {
                cw[warp * 64 + nf * 8 + 2 * lane    ] = cs[nf][0];
                cw[warp * 64 + nf * 8 + 2 * lane + 1] = cs[nf][1];
            }
        }
        __syncthreads();
        int j  = tid & 63;
        int h  = (tid >> 6) & 1;
        int mp = tid >> 7;
        float v = cw[(h + 4 * mp) * 64 + j] + cw[(h + 4 * mp + 2) * 64 + j];
        g_rowpart[(size_t)(2 * x + mp) * N_TOTAL + (col0 + h * 64 + j)] = v;
    }
}

// ---------------------------------------------------------------------------
// Kernel 3: per-row loss + fused deterministic final reduction.
// grid 256 x 256; block handles 32 rows. Phase 1: warp w sums slots
// [16w, 16w+16) over 32 consecutive rows (coalesced in [slot][row]).
// Phase 2: 8 threads per row compute diag/pos; p==0 folds the 8 slot
// partials (fixed order) and the lse term.
// ---------------------------------------------------------------------------
__global__ __launch_bounds__(256) void rowloss_kernel(float* __restrict__ out) {
    __shared__ float ws[8][32];
    __shared__ float rl[32];
    __shared__ int s_last;
    int tid  = threadIdx.x;
    int w    = tid >> 5;
    int lane = tid & 31;
    int rbase = blockIdx.x * 32;

    float accp = 0.f;
    #pragma unroll
    for (int s = 0; s < 16; ++s)
        accp += g_rowpart[(size_t)(w * 16 + s) * N_TOTAL + rbase + lane];
    ws[w][lane] = accp;
    __syncthreads();

    int r = tid >> 3;                    // 0..31
    int p = tid & 7;
    int grow = rbase + r;
    int prow = (grow < 4096) ? grow + 4096 : grow - 4096;
    const uint4* ap = reinterpret_cast<const uint4*>(g_zb + (size_t)grow * DK);
    const uint4* bp = reinterpret_cast<const uint4*>(g_zb + (size_t)prow * DK);
    float diag = 0.f, pos = 0.f;         // scaled units
    #pragma unroll
    for (int q = 0; q < 4; ++q) {
        uint4 a4 = ap[p * 4 + q];
        uint4 b4 = bp[p * 4 + q];
        const uint32_t* au = &a4.x;
        const uint32_t* bu = &b4.x;
        #pragma unroll
        for (int k = 0; k < 4; ++k) {
            __nv_bfloat162 a2 = *reinterpret_cast<const __nv_bfloat162*>(&au[k]);
            __nv_bfloat162 b2 = *reinterpret_cast<const __nv_bfloat162*>(&bu[k]);
            float ax = __bfloat162float(a2.x), ay = __bfloat162float(a2.y);
            float bx = __bfloat162float(b2.x), by = __bfloat162float(b2.y);
            diag += ax * ax + ay * ay;
            pos  += ax * bx + ay * by;
        }
    }
    #pragma unroll
    for (int o = 1; o < 8; o <<= 1) {    // reduce within the 8-thread group
        diag += __shfl_xor_sync(0xffffffffu, diag, o);
        pos  += __shfl_xor_sync(0xffffffffu, pos,  o);
    }
    if (p == 0) {
        float se = 0.f;
        #pragma unroll
        for (int i = 0; i < 8; ++i) se += ws[i][r];
        float sv = se - fast_exp2(diag); // same exp formula -> cancels
        rl[r] = __logf(sv) - pos * 0.6931471805599453f;
    }
    __syncthreads();
    if (tid == 0) {
        float s = 0.f;
        #pragma unroll
        for (int i = 0; i < 32; ++i) s += rl[i];
        g_partial[blockIdx.x] = s;
        __threadfence();
        s_last = (atomicAdd(&g_done, 1) == (int)gridDim.x - 1);
    }
    __syncthreads();

    if (s_last) {
        __shared__ float red[256];
        red[tid] = g_partial[tid];
        __syncthreads();
        #pragma unroll
        for (int o = 128; o; o >>= 1) {
            if (tid < o) red[tid] += red[tid + o];
            __syncthreads();
        }
        if (tid == 0) out[0] = red[0] * (1.0f / (float)N_TOTAL);
    }
}

// ---------------------------------------------------------------------------
extern "C" void kernel_launch(void* const* d_in, const int* in_sizes, int n_in,
                              void* d_out, int out_size)
{
    const float* zi = (const float*)d_in[0];
    const float* zj = (const float*)d_in[1];
    float* out = (float*)d_out;

    cudaFuncSetAttribute(simexp_kernel,
                         cudaFuncAttributeMaxDynamicSharedMemorySize, SMEM_BYTES);

    normalize_kernel<<<1024, 256>>>(zi, zj);
    simexp_kernel<<<NTRI, 256, SMEM_BYTES>>>();
    rowloss_kernel<<<256, 256>>>(out);
}

// round 14
// speedup vs baseline: 1.2570x; 1.0006x over previous
#include <cuda_runtime.h>
#include <cuda_bf16.h>
#include <cstdint>

// ===========================================================================
// NT-Xent (SimCLR) loss, B=4096, D=256, T=0.5  ->  N=8192 rows, K=256.
//
// R13 = R12 (best: 55.8us) with normalize rebuilt for MLP:
//   * 8 threads/row, 8 independent float4 loads in flight per thread
//     (was 2), 3-shfl group reduction, coalesced 8B stores.
// simexp mainloop FROZEN: tensor pipe + smem crossbar are co-saturated
// (cp.async writes + LDSM fragment duplication ~= 128B/cyc budget); without
// tcgen05/TMEM (unreachable on plain compute_103) this is the floor.
// Persistence dead (R5/R11), dtype levers dead (R7/R9), interleave neutral
// (R10), [slot][row] transpose won (R12).
//
// Triangle trick: 2080 upper 128x128 tiles; off-diag tiles emit row+col sums.
// Logit scale folded into inputs (zb = z_hat*sqrt(2*log2 e)); diagonal
// subtracted later with the SAME ex2 formula (cancels to rounding).
// ===========================================================================

#define N_TOTAL 8192
#define DK      256
#define TILE    128
#define NTILES  64
#define NSLOTS  (NTILES * 2)                    // 128 partial slots per row
#define NTRI    (NTILES * (NTILES + 1) / 2)     // 2080 triangle tiles

#define SCALE_S 1.6986435987381852f             // sqrt(2*log2(e))

__device__ __nv_bfloat16 g_zb[(size_t)N_TOTAL * DK];        // 4 MB
__device__ float g_rowpart[(size_t)NSLOTS * N_TOTAL];       // 4 MB, [slot][row]
__device__ float g_partial[256];
__device__ int   g_done;

// ---------------------------------------------------------------------------
__device__ __forceinline__ uint32_t smem_u32(const void* p) {
    uint32_t a;
    asm("{ .reg .u64 t; cvta.to.shared.u64 t, %1; cvt.u32.u64 %0, t; }"
        : "=r"(a) : "l"(p));
    return a;
}

__device__ __forceinline__ float fast_exp2(float x) {
    float y;
    asm("ex2.approx.f32 %0, %1;" : "=f"(y) : "f"(x));
    return y;
}

#define LDSM_X4(r, addr) \
    asm volatile("ldmatrix.sync.aligned.m8n8.x4.shared.b16 {%0,%1,%2,%3}, [%4];" \
        : "=r"((r)[0]), "=r"((r)[1]), "=r"((r)[2]), "=r"((r)[3]) : "r"(addr))

#define MMA16816(c, a, b0v, b1v) \
    asm volatile("mma.sync.aligned.m16n8k16.row.col.f32.bf16.bf16.f32 " \
        "{%0,%1,%2,%3}, {%4,%5,%6,%7}, {%8,%9}, {%0,%1,%2,%3};" \
        : "+f"((c)[0]), "+f"((c)[1]), "+f"((c)[2]), "+f"((c)[3]) \
        : "r"((a)[0]), "r"((a)[1]), "r"((a)[2]), "r"((a)[3]), \
          "r"(b0v), "r"(b1v))

__device__ __forceinline__ void cp16(uint32_t saddr, const void* gptr) {
    uint64_t g;
    asm volatile("cvta.to.global.u64 %0, %1;" : "=l"(g) : "l"(gptr));
    asm volatile("cp.async.cg.shared.global [%0], [%1], 16;"
                 :: "r"(saddr), "l"(g) : "memory");
}
template <int N>
__device__ __forceinline__ void cp_wait() {
    asm volatile("cp.async.wait_group %0;" :: "n"(N) : "memory");
}
__device__ __forceinline__ void cp_commit() {
    asm volatile("cp.async.commit_group;" ::: "memory");
}

// ---------------------------------------------------------------------------
// Kernel 1: normalize rows -> bf16 (pre-scaled by SCALE_S), reset done ctr.
// 8 threads per row; 8 float4 loads in flight per thread (MLP=8).
// grid 256 x 256: block covers 32 rows; warp covers 4 rows, each load
// instruction touches 4 contiguous 128B segments.
// ---------------------------------------------------------------------------
__global__ __launch_bounds__(256) void normalize_kernel(
    const float* __restrict__ zi, const float* __restrict__ zj)
{
    if (blockIdx.x == 0 && threadIdx.x == 0) g_done = 0;
    int row = blockIdx.x * 32 + (threadIdx.x >> 3);
    int p   = threadIdx.x & 7;
    const float* src = (row < 4096) ? zi + (size_t)row * DK
                                    : zj + (size_t)(row - 4096) * DK;
    // 8 independent loads, all issued before any use
    float4 v[8];
    #pragma unroll
    for (int i = 0; i < 8; ++i)
        v[i] = reinterpret_cast<const float4*>(src)[i * 8 + p];

    float ss = 0.f;
    #pragma unroll
    for (int i = 0; i < 8; ++i)
        ss += v[i].x * v[i].x + v[i].y * v[i].y
            + v[i].z * v[i].z + v[i].w * v[i].w;
    #pragma unroll
    for (int o = 1; o < 8; o <<= 1)      // reduce within the 8-thread group
        ss += __shfl_xor_sync(0xffffffffu, ss, o);
    float rn = rsqrtf(ss) * SCALE_S;

    uint2* dst = reinterpret_cast<uint2*>(g_zb + (size_t)row * DK);
    #pragma unroll
    for (int i = 0; i < 8; ++i) {
        __nv_bfloat162 q0 = __floats2bfloat162_rn(v[i].x * rn, v[i].y * rn);
        __nv_bfloat162 q1 = __floats2bfloat162_rn(v[i].z * rn, v[i].w * rn);
        uint2 o2;
        o2.x = *reinterpret_cast<uint32_t*>(&q0);
        o2.y = *reinterpret_cast<uint32_t*>(&q1);
        dst[i * 8 + p] = o2;
    }
}

// ---------------------------------------------------------------------------
// Kernel 2 (R12 verbatim): upper-triangle 128x128 HMMA tiles +
// exp row/col sums. 2080 CTAs, 256 threads (8 warps, 4(M) x 2(N)).
// K=256 in 4 chunks of 64 via 3-stage cp.async (96 KB smem, 2 CTAs/SM),
// ONE __syncthreads per chunk. Epilogue stores to [slot][row] (coalesced).
// ---------------------------------------------------------------------------
#define KCHUNK      64
#define MAT_BYTES   (TILE * KCHUNK * 2)          // 16384
#define STAGE_BYTES (2 * MAT_BYTES)              // 32768
#define NSTAGE      3
#define CW_OFF      (NSTAGE * STAGE_BYTES)       // 98304
#define SMEM_BYTES  (CW_OFF + 2048)              // 100352

__device__ __forceinline__ uint32_t sw_off(int r, int kg) {
    return (uint32_t)(r * 128 + ((kg ^ (r & 7)) << 4));
}

__device__ __forceinline__ void prefetch_chunk(
    uint32_t sbase, int stage, int row0, int col0, int chunk, int tid)
{
    #pragma unroll
    for (int i = 0; i < 8; ++i) {
        int v   = tid + i * 256;         // 0..2047
        int mat = v >> 10;               // 0 = A, 1 = B
        int r   = (v >> 3) & 127;
        int kg  = v & 7;
        int grow = (mat ? col0 : row0) + r;
        const __nv_bfloat16* g = g_zb + (size_t)grow * DK + chunk * KCHUNK + kg * 8;
        uint32_t s = sbase + stage * STAGE_BYTES + mat * MAT_BYTES + sw_off(r, kg);
        cp16(s, g);
    }
    cp_commit();
}

__global__ __launch_bounds__(256, 2) void simexp_kernel() {
    extern __shared__ char smem[];
    const uint32_t sbase = smem_u32(smem);
    const int tid  = threadIdx.x;
    const int warp = tid >> 5;
    const int lane = tid & 31;

    // --- decode linear tile id -> (x, y) with y >= x; start(x)=x*(129-x)/2 ---
    const int t = blockIdx.x;
    int x = __float2int_rd((129.0f - sqrtf(16641.0f - 8.0f * (float)t)) * 0.5f);
    if (x > 63) x = 63;
    while (x > 0 && x * (129 - x) / 2 > t) --x;
    while ((x + 1) * (129 - (x + 1)) / 2 <= t) ++x;
    const int y = x + (t - x * (129 - x) / 2);

    const int row0 = x * TILE;
    const int col0 = y * TILE;
    const int warp_m = (warp >> 1) * 32;
    const int warp_n = (warp & 1) * 64;

    float acc[2][8][4];
    #pragma unroll
    for (int mf = 0; mf < 2; ++mf)
        #pragma unroll
        for (int nf = 0; nf < 8; ++nf)
            #pragma unroll
            for (int q = 0; q < 4; ++q) acc[mf][nf][q] = 0.f;

    prefetch_chunk(sbase, 0, row0, col0, 0, tid);
    prefetch_chunk(sbase, 1, row0, col0, 1, tid);

    #pragma unroll
    for (int c = 0; c < 4; ++c) {
        if (c < 3) { cp_wait<1>(); } else { cp_wait<0>(); }
        __syncthreads();                 // chunk c resident; chunk c-1 done by
                                         // all warps -> c+2 prefetch is safe
        if (c + 2 < 4)
            prefetch_chunk(sbase, (c + 2) % NSTAGE, row0, col0, c + 2, tid);

        const uint32_t abase = sbase + (c % NSTAGE) * STAGE_BYTES;
        const uint32_t bbase = abase + MAT_BYTES;

        #pragma unroll
        for (int ks = 0; ks < 4; ++ks) {
            uint32_t afr[2][4];
            #pragma unroll
            for (int mf = 0; mf < 2; ++mf) {
                int r  = warp_m + mf * 16 + (lane & 15);
                int kg = 2 * ks + (lane >> 4);
                LDSM_X4(afr[mf], abase + sw_off(r, kg));
            }
            uint32_t bfr[4][4];
            #pragma unroll
            for (int nb = 0; nb < 4; ++nb) {
                int n  = warp_n + nb * 16 + ((lane >> 4) << 3) + (lane & 7);
                int kg = 2 * ks + ((lane >> 3) & 1);
                LDSM_X4(bfr[nb], bbase + sw_off(n, kg));
            }
            #pragma unroll
            for (int mf = 0; mf < 2; ++mf)
                #pragma unroll
                for (int nb = 0; nb < 4; ++nb) {
                    MMA16816(acc[mf][2 * nb    ], afr[mf], bfr[nb][0], bfr[nb][1]);
                    MMA16816(acc[mf][2 * nb + 1], afr[mf], bfr[nb][2], bfr[nb][3]);
                }
        }
    }

    // --- Epilogue ---
    float rs[4] = {0.f, 0.f, 0.f, 0.f};
    float cs[8][2];
    #pragma unroll
    for (int nf = 0; nf < 8; ++nf) { cs[nf][0] = 0.f; cs[nf][1] = 0.f; }

    #pragma unroll
    for (int mf = 0; mf < 2; ++mf)
        #pragma unroll
        for (int nf = 0; nf < 8; ++nf) {
            float e0 = fast_exp2(acc[mf][nf][0]);
            float e1 = fast_exp2(acc[mf][nf][1]);
            float e2 = fast_exp2(acc[mf][nf][2]);
            float e3 = fast_exp2(acc[mf][nf][3]);
            rs[mf * 2 + 0] += e0 + e1;
            rs[mf * 2 + 1] += e2 + e3;
            cs[nf][0] += e0 + e2;
            cs[nf][1] += e1 + e3;
        }

    #pragma unroll
    for (int o = 1; o < 4; o <<= 1)
        #pragma unroll
        for (int q = 0; q < 4; ++q)
            rs[q] += __shfl_xor_sync(0xffffffffu, rs[q], o);
    if ((lane & 3) == 0) {
        int g    = lane >> 2;
        int slot = 2 * y + (warp & 1);
        // [slot][row] layout: 8 lanes write 8 consecutive floats -> 1 sector
        g_rowpart[(size_t)slot * N_TOTAL + (row0 + warp_m +  0 + g)] = rs[0];
        g_rowpart[(size_t)slot * N_TOTAL + (row0 + warp_m +  8 + g)] = rs[1];
        g_rowpart[(size_t)slot * N_TOTAL + (row0 + warp_m + 16 + g)] = rs[2];
        g_rowpart[(size_t)slot * N_TOTAL + (row0 + warp_m + 24 + g)] = rs[3];
    }

    if (x != y) {
        #pragma unroll
        for (int o = 4; o < 32; o <<= 1)
            #pragma unroll
            for (int nf = 0; nf < 8; ++nf) {
                cs[nf][0] += __shfl_xor_sync(0xffffffffu, cs[nf][0], o);
                cs[nf][1] += __shfl_xor_sync(0xffffffffu, cs[nf][1], o);
            }
        float* cw = reinterpret_cast<float*>(smem + CW_OFF);
        if (lane < 4) {
            #pragma unroll
            for (int nf = 0; nf < 8; ++nf) {
                cw[warp * 64 + nf * 8 + 2 * lane    ] = cs[nf][0];
                cw[warp * 64 + nf * 8 + 2 * lane + 1] = cs[nf][1];
            }
        }
        __syncthreads();
        int j  = tid & 63;
        int h  = (tid >> 6) & 1;
        int mp = tid >> 7;
        float v = cw[(h + 4 * mp) * 64 + j] + cw[(h + 4 * mp + 2) * 64 + j];
        g_rowpart[(size_t)(2 * x + mp) * N_TOTAL + (col0 + h * 64 + j)] = v;
    }
}

// ---------------------------------------------------------------------------
// Kernel 3 (R12 verbatim): per-row loss + fused deterministic final reduce.
// ---------------------------------------------------------------------------
__global__ __launch_bounds__(256) void rowloss_kernel(float* __restrict__ out) {
    __shared__ float ws[8][32];
    __shared__ float rl[32];
    __shared__ int s_last;
    int tid  = threadIdx.x;
    int w    = tid >> 5;
    int lane = tid & 31;
    int rbase = blockIdx.x * 32;

    float accp = 0.f;
    #pragma unroll
    for (int s = 0; s < 16; ++s)
        accp += g_rowpart[(size_t)(w * 16 + s) * N_TOTAL + rbase + lane];
    ws[w][lane] = accp;
    __syncthreads();

    int r = tid >> 3;                    // 0..31
    int p = tid & 7;
    int grow = rbase + r;
    int prow = (grow < 4096) ? grow + 4096 : grow - 4096;
    const uint4* ap = reinterpret_cast<const uint4*>(g_zb + (size_t)grow * DK);
    const uint4* bp = reinterpret_cast<const uint4*>(g_zb + (size_t)prow * DK);
    float diag = 0.f, pos = 0.f;         // scaled units
    #pragma unroll
    for (int q = 0; q < 4; ++q) {
        uint4 a4 = ap[p * 4 + q];
        uint4 b4 = bp[p * 4 + q];
        const uint32_t* au = &a4.x;
        const uint32_t* bu = &b4.x;
        #pragma unroll
        for (int k = 0; k < 4; ++k) {
            __nv_bfloat162 a2 = *reinterpret_cast<const __nv_bfloat162*>(&au[k]);
            __nv_bfloat162 b2 = *reinterpret_cast<const __nv_bfloat162*>(&bu[k]);
            float ax = __bfloat162float(a2.x), ay = __bfloat162float(a2.y);
            float bx = __bfloat162float(b2.x), by = __bfloat162float(b2.y);
            diag += ax * ax + ay * ay;
            pos  += ax * bx + ay * by;
        }
    }
    #pragma unroll
    for (int o = 1; o < 8; o <<= 1) {    // reduce within the 8-thread group
        diag += __shfl_xor_sync(0xffffffffu, diag, o);
        pos  += __shfl_xor_sync(0xffffffffu, pos,  o);
    }
    if (p == 0) {
        float se = 0.f;
        #pragma unroll
        for (int i = 0; i < 8; ++i) se += ws[i][r];
        float sv = se - fast_exp2(diag); // same exp formula -> cancels
        rl[r] = __logf(sv) - pos * 0.6931471805599453f;
    }
    __syncthreads();
    if (tid == 0) {
        float s = 0.f;
        #pragma unroll
        for (int i = 0; i < 32; ++i) s += rl[i];
        g_partial[blockIdx.x] = s;
        __threadfence();
        s_last = (atomicAdd(&g_done, 1) == (int)gridDim.x - 1);
    }
    __syncthreads();

    if (s_last) {
        __shared__ float red[256];
        red[tid] = g_partial[tid];
        __syncthreads();
        #pragma unroll
        for (int o = 128; o; o >>= 1) {
            if (tid < o) red[tid] += red[tid + o];
            __syncthreads();
        }
        if (tid == 0) out[0] = red[0] * (1.0f / (float)N_TOTAL);
    }
}

// ---------------------------------------------------------------------------
extern "C" void kernel_launch(void* const* d_in, const int* in_sizes, int n_in,
                              void* d_out, int out_size)
{
    const float* zi = (const float*)d_in[0];
    const float* zj = (const float*)d_in[1];
    float* out = (float*)d_out;

    cudaFuncSetAttribute(simexp_kernel,
                         cudaFuncAttributeMaxDynamicSharedMemorySize, SMEM_BYTES);

    normalize_kernel<<<256, 256>>>(zi, zj);
    simexp_kernel<<<NTRI, 256, SMEM_BYTES>>>();
    rowloss_kernel<<<256, 256>>>(out);
}